// round 5
// baseline (speedup 1.0000x reference)
#include <cuda_runtime.h>
#include <cstdint>
#include <cstddef>

// Problem dims
#define Bc 256
#define Tc 128
#define Hc 1024
#define Vc 64
#define Lc 457
#define ML 64

typedef unsigned long long ull;

// ---------------- device scratch (no allocs allowed) ----------------
__device__ float g_U0[(size_t)Bc * Tc * Hc];   // x @ enc_Wih0^T + b0
__device__ float g_h0[2][Bc * Hc];
__device__ float g_h1[2][Bc * Hc];
__device__ float g_V [2][Bc * Hc];             // h0_t @ eWih1^T + b1
__device__ float g_d0[2][Bc * Hc];
__device__ float g_d1[2][Bc * Hc];
__device__ float g_P0[Bc * Hc];                // d0_{s-1} @ dWhh0^T
__device__ float g_P1[Bc * Hc];                // d1_{s-1} @ dWhh1^T
__device__ float g_zero[Bc * Hc];
__device__ int   g_tok[Bc];

// ---------------- packed fp32 helpers (sm_103a f32x2) ----------------
__device__ __forceinline__ void ffma2(ull& d, ull a, ull b) {
    asm("fma.rn.f32x2 %0, %1, %2, %0;" : "+l"(d) : "l"(a), "l"(b));
}
__device__ __forceinline__ void unpk(ull v, float& lo, float& hi) {
    unsigned int a, b;
    asm("mov.b64 {%0, %1}, %2;" : "=r"(a), "=r"(b) : "l"(v));
    lo = __uint_as_float(a);
    hi = __uint_as_float(b);
}

// ---------------- GEMM job descriptor (single source) ----------------
struct GemmJob {
    const float* A; long lda; const float* W;  // C = act(A @ W^T + bias + addmat)
    int K;
    const int* gather;                          // optional row gather on A
    const float* bias; const float* addmat; long ldadd;
    float* C; long ldc; int act; int valid;
};

// ---------------- tile loaders (BR rows x KB k-cols) ----------------
template<int NT, int BR, int KB>
__device__ __forceinline__ void load_tile(
    const float* __restrict__ A, long lda, const int* __restrict__ gather,
    int r_base, int K, int k0, int tid, float (&r)[BR * KB / 4 / NT][4])
{
    constexpr int NC = BR * KB / 4 / NT;
    constexpr int KQ = KB / 4;
#pragma unroll
    for (int i = 0; i < NC; i++) {
        int cid = tid + i * NT;
        int row = cid / KQ, kq = cid % KQ;
        int kk = k0 + kq * 4;
        long arow = gather ? (long)__ldg(&gather[r_base + row]) : (long)(r_base + row);
        const float* p = A + arow * lda + kk;
        if (kk + 3 < K && ((((uintptr_t)p) & 15u) == 0)) {
            float4 v = *(const float4*)p;
            r[i][0] = v.x; r[i][1] = v.y; r[i][2] = v.z; r[i][3] = v.w;
        } else {
#pragma unroll
            for (int j = 0; j < 4; j++)
                r[i][j] = (kk + j < K) ? __ldg(p + j) : 0.0f;
        }
    }
}

// A stored naturally: As[k][row] (row pairs read as packed f32x2 later)
template<int NT, int BR, int KB>
__device__ __forceinline__ void store_a(
    float (&S)[KB][BR], int tid, const float (&r)[BR * KB / 4 / NT][4])
{
    constexpr int NC = BR * KB / 4 / NT;
    constexpr int KQ = KB / 4;
#pragma unroll
    for (int i = 0; i < NC; i++) {
        int cid = tid + i * NT;
        int row = cid / KQ, kq = cid % KQ;
#pragma unroll
        for (int j = 0; j < 4; j++)
            S[kq * 4 + j][row] = r[i][j];
    }
}

// W stored duplicated: Ws2[k][2*col] = Ws2[k][2*col+1] = v (b operand of f32x2)
template<int NT, int BR, int KB>
__device__ __forceinline__ void store_w_dup(
    float (&S)[KB][2 * BR], int tid, const float (&r)[BR * KB / 4 / NT][4])
{
    constexpr int NC = BR * KB / 4 / NT;
    constexpr int KQ = KB / 4;
#pragma unroll
    for (int i = 0; i < NC; i++) {
        int cid = tid + i * NT;
        int row = cid / KQ, kq = cid % KQ;
#pragma unroll
        for (int j = 0; j < 4; j++) {
            float v = r[i][j];
            *(float2*)&S[kq * 4 + j][2 * row] = make_float2(v, v);
        }
    }
}

// ---------------- micro-kernel: M-packed f32x2 ----------------
// acc[p][n] = packed {C[r0+2p][c0+n], C[r0+2p+1][c0+n]}
template<int BM, int BN, int TM, int TN, int KB>
__device__ __forceinline__ void mac_block(
    const float (&As)[KB][BM], const float (&Ws2)[KB][2 * BN],
    int r0, int c0, ull (&acc)[TM / 2][TN])
{
#pragma unroll
    for (int k = 0; k < KB; k++) {
        ull ad[TM / 2];
        if constexpr (TM == 2) {
            ad[0] = *(const ull*)&As[k][r0];
        } else {
#pragma unroll
            for (int i = 0; i < TM / 4; i++) {
                ulonglong2 t = *(const ulonglong2*)&As[k][r0 + 4 * i];
                ad[2 * i] = t.x; ad[2 * i + 1] = t.y;
            }
        }
        ull wv[TN];
#pragma unroll
        for (int n2 = 0; n2 < TN / 2; n2++) {
            ulonglong2 w = *(const ulonglong2*)&Ws2[k][2 * c0 + 4 * n2];
            wv[2 * n2] = w.x; wv[2 * n2 + 1] = w.y;
        }
#pragma unroll
        for (int p = 0; p < TM / 2; p++)
#pragma unroll
            for (int n = 0; n < TN; n++)
                ffma2(acc[p][n], ad[p], wv[n]);
    }
}

// ---------------- K-staged mainloop ----------------
template<int NT, int BM, int BN, int TM, int TN, int KB>
__device__ __forceinline__ void gemm_mainloop(
    const float* __restrict__ A, long lda,
    const float* __restrict__ W, int K,
    const int* __restrict__ gather,
    int m0, int n0, int tid, int r0, int c0,
    float (&As)[2][KB][BM], float (&Ws2)[2][KB][2 * BN],
    ull (&acc)[TM / 2][TN])
{
    constexpr int NCA = BM * KB / 4 / NT;
    constexpr int NCW = BN * KB / 4 / NT;
    float ar[NCA][4], wr[NCW][4];
    int nkb = (K + KB - 1) / KB;

    load_tile<NT, BM, KB>(A, lda, gather, m0, K, 0, tid, ar);
    load_tile<NT, BN, KB>(W, (long)K, nullptr, n0, K, 0, tid, wr);
    store_a<NT, BM, KB>(As[0], tid, ar);
    store_w_dup<NT, BN, KB>(Ws2[0], tid, wr);
    __syncthreads();

    int buf = 0;
    for (int kb = 0; kb < nkb; kb++) {
        bool hn = (kb + 1 < nkb);
        if (hn) {
            load_tile<NT, BM, KB>(A, lda, gather, m0, K, (kb + 1) * KB, tid, ar);
            load_tile<NT, BN, KB>(W, (long)K, nullptr, n0, K, (kb + 1) * KB, tid, wr);
        }
        mac_block<BM, BN, TM, TN, KB>(As[buf], Ws2[buf], r0, c0, acc);
        if (hn) {
            store_a<NT, BM, KB>(As[buf ^ 1], tid, ar);
            store_w_dup<NT, BN, KB>(Ws2[buf ^ 1], tid, wr);
        }
        __syncthreads();
        buf ^= 1;
    }
}

// ---------------- generic GEMM kernel: up to 3 jobs via blockIdx.z ----------------
template<int NT, int BM, int BN, int TM, int TN, int KB>
__global__ void __launch_bounds__(NT)
gemm3_kernel(GemmJob j0, GemmJob j1, GemmJob j2)
{
    GemmJob j = (blockIdx.z == 0) ? j0 : ((blockIdx.z == 1) ? j1 : j2);
    if (!j.valid) return;

    __shared__ float As[2][KB][BM];
    __shared__ float Ws2[2][KB][2 * BN];

    constexpr int CT = BN / TN;
    int tid = threadIdx.x;
    int m0 = blockIdx.y * BM;
    int n0 = blockIdx.x * BN;
    int ty = tid / CT, tx = tid % CT;
    int r0 = ty * TM, c0 = tx * TN;

    ull acc[TM / 2][TN] = {};
    gemm_mainloop<NT, BM, BN, TM, TN, KB>(j.A, j.lda, j.W, j.K, j.gather,
                                          m0, n0, tid, r0, c0, As, Ws2, acc);

#pragma unroll
    for (int p = 0; p < TM / 2; p++) {
        float lo[TN], hi[TN];
#pragma unroll
        for (int n = 0; n < TN; n++) unpk(acc[p][n], lo[n], hi[n]);
        int m_lo = m0 + r0 + 2 * p;
        int m_hi = m_lo + 1;
#pragma unroll
        for (int n = 0; n < TN; n++) {
            int col = n0 + c0 + n;
            float bv = j.bias ? __ldg(&j.bias[col]) : 0.0f;
            float vl = lo[n] + bv;
            float vh = hi[n] + bv;
            if (j.addmat) {
                vl += __ldg(&j.addmat[(long)m_lo * j.ldadd + col]);
                vh += __ldg(&j.addmat[(long)m_hi * j.ldadd + col]);
            }
            if (j.act) { vl = tanhf(vl); vh = tanhf(vh); }
            lo[n] = vl; hi[n] = vh;
        }
#pragma unroll
        for (int n = 0; n < TN; n += 4) {
            *(float4*)&j.C[(long)m_lo * j.ldc + n0 + c0 + n] = *(const float4*)&lo[n];
            *(float4*)&j.C[(long)m_hi * j.ldc + n0 + c0 + n] = *(const float4*)&hi[n];
        }
    }
}

// ---------------- fused logits + argmax (tiled GEMM, 8 blocks) ----------------
__global__ void __launch_bounds__(256)
logits_kernel(const float* __restrict__ d1, const float* __restrict__ fcW,
              const float* __restrict__ fcb, float* __restrict__ out,
              int step, int* __restrict__ tok)
{
    constexpr int NT = 256, BM = 32, BN = 64, TM = 2, TN = 4, KB = 32;
    __shared__ float As[2][KB][BM];
    __shared__ float Ws2[2][KB][2 * BN];
    __shared__ float vals[BM][BN + 1];

    constexpr int CT = BN / TN;  // 16
    int tid = threadIdx.x;
    int m0 = blockIdx.x * BM;
    int ty = tid / CT, tx = tid % CT;
    int r0 = ty * TM, c0 = tx * TN;

    ull acc[TM / 2][TN] = {};
    gemm_mainloop<NT, BM, BN, TM, TN, KB>(d1, (long)Hc, fcW, Hc, nullptr,
                                          m0, 0, tid, r0, c0, As, Ws2, acc);

#pragma unroll
    for (int n = 0; n < TN; n++) {
        float lo, hi;
        unpk(acc[0][n], lo, hi);
        int v = c0 + n;
        float bv = __ldg(&fcb[v]);
        lo += bv; hi += bv;
        int b_lo = m0 + r0, b_hi = b_lo + 1;
        vals[r0][v] = lo;
        vals[r0 + 1][v] = hi;
        out[((size_t)b_lo * Vc + (size_t)v) * ML + (size_t)step] = lo;
        out[((size_t)b_hi * Vc + (size_t)v) * ML + (size_t)step] = hi;
    }
    __syncthreads();
    if (tid < BM) {
        float best = vals[tid][0];
        int bi = 0;
#pragma unroll
        for (int i = 1; i < Vc; i++) {
            float v = vals[tid][i];
            if (v > best) { best = v; bi = i; }   // first-max = jnp.argmax
        }
        tok[m0 + tid] = bi;
    }
}

__global__ void init_kernel(float* __restrict__ z, int* __restrict__ tok)
{
    int i = blockIdx.x * blockDim.x + threadIdx.x;
    if (i < Bc * Hc) z[i] = 0.0f;
    if (i < Bc) tok[i] = 0;
}

__global__ void copy_hidden_kernel(const float* __restrict__ d0,
                                   const float* __restrict__ d1,
                                   float* __restrict__ o)
{
    int i = blockIdx.x * blockDim.x + threadIdx.x;
    if (i < Bc * Hc) {
        o[i] = d0[i];
        o[Bc * Hc + i] = d1[i];
    }
}

// ---------------- host ----------------
extern "C" void kernel_launch(void* const* d_in, const int* in_sizes, int n_in,
                              void* d_out, int out_size)
{
    (void)in_sizes; (void)n_in; (void)out_size;
    const float* x     = (const float*)d_in[0];
    const float* emb   = (const float*)d_in[1];
    const float* eWih0 = (const float*)d_in[2];
    const float* eWhh0 = (const float*)d_in[3];
    const float* eb0   = (const float*)d_in[4];
    const float* eWih1 = (const float*)d_in[5];
    const float* eWhh1 = (const float*)d_in[6];
    const float* eb1   = (const float*)d_in[7];
    const float* dWih0 = (const float*)d_in[8];
    const float* dWhh0 = (const float*)d_in[9];
    const float* db0   = (const float*)d_in[10];
    const float* dWih1 = (const float*)d_in[11];
    const float* dWhh1 = (const float*)d_in[12];
    const float* db1   = (const float*)d_in[13];
    const float* fcW   = (const float*)d_in[14];
    const float* fcb   = (const float*)d_in[15];
    float* out = (float*)d_out;

    float *U0, *h0base, *h1base, *Vbase, *d0base, *d1base, *P0, *P1, *zero;
    int* tok;
    cudaGetSymbolAddress((void**)&U0, g_U0);
    cudaGetSymbolAddress((void**)&h0base, g_h0);
    cudaGetSymbolAddress((void**)&h1base, g_h1);
    cudaGetSymbolAddress((void**)&Vbase, g_V);
    cudaGetSymbolAddress((void**)&d0base, g_d0);
    cudaGetSymbolAddress((void**)&d1base, g_d1);
    cudaGetSymbolAddress((void**)&P0, g_P0);
    cudaGetSymbolAddress((void**)&P1, g_P1);
    cudaGetSymbolAddress((void**)&zero, g_zero);
    cudaGetSymbolAddress((void**)&tok, g_tok);

    float* h0b[2] = { h0base, h0base + (size_t)Bc * Hc };
    float* h1b[2] = { h1base, h1base + (size_t)Bc * Hc };
    float* Vb[2]  = { Vbase,  Vbase  + (size_t)Bc * Hc };
    float* d0b[2] = { d0base, d0base + (size_t)Bc * Hc };
    float* d1b[2] = { d1base, d1base + (size_t)Bc * Hc };

    init_kernel<<<(Bc * Hc + 255) / 256, 256>>>(zero, tok);

    GemmJob inv = {}; inv.valid = 0;

    // ---- precompute U0 = x_flat @ eWih0^T + b0 ----
    {
        GemmJob j = {};
        j.A = x; j.lda = Lc; j.W = eWih0; j.K = Lc;
        j.bias = eb0;
        j.C = U0; j.ldc = Hc; j.act = 0; j.valid = 1;
        gemm3_kernel<256, 128, 64, 8, 4, 32>
            <<<dim3(Hc / 64, (Bc * Tc) / 128, 1), 256>>>(j, inv, inv);
    }

    // ---- encoder: 3 balanced units per launch (skewed dependency chain) ----
    // launch t: A) h0_t = tanh(h0_{t-1}@Whh0 + U0[:,t])
    //           B) V_{t-1} = h0_{t-1}@Wih1 + b1
    //           C) h1_{t-2} = tanh(h1_{t-3}@Whh1 + V_{t-2})
    // t == Tc: slot A computes decoder bootstrap P0_0 = h0_final @ dWhh0
    for (int t = 0; t <= Tc + 1; t++) {
        GemmJob jA = inv, jB = inv, jC = inv;
        if (t < Tc) {
            jA.A = (t == 0) ? zero : h0b[(t - 1) & 1];
            jA.lda = Hc; jA.W = eWhh0; jA.K = Hc;
            jA.addmat = U0 + (size_t)t * Hc; jA.ldadd = (long)Tc * Hc;
            jA.C = h0b[t & 1]; jA.ldc = Hc; jA.act = 1; jA.valid = 1;
        } else if (t == Tc) {
            jA.A = h0b[(Tc - 1) & 1]; jA.lda = Hc; jA.W = dWhh0; jA.K = Hc;
            jA.C = P0; jA.ldc = Hc; jA.act = 0; jA.valid = 1;
        }
        if (t >= 1 && t <= Tc) {
            int s = t - 1;
            jB.A = h0b[s & 1]; jB.lda = Hc; jB.W = eWih1; jB.K = Hc;
            jB.bias = eb1;
            jB.C = Vb[s & 1]; jB.ldc = Hc; jB.act = 0; jB.valid = 1;
        }
        if (t >= 2) {
            int s = t - 2;
            jC.A = (s == 0) ? zero : h1b[(s - 1) & 1];
            jC.lda = Hc; jC.W = eWhh1; jC.K = Hc;
            jC.addmat = Vb[s & 1]; jC.ldadd = Hc;
            jC.C = h1b[s & 1]; jC.ldc = Hc; jC.act = 1; jC.valid = 1;
        }
        gemm3_kernel<128, 64, 64, 8, 4, 32>
            <<<dim3(Hc / 64, Bc / 64, 3), 128>>>(jA, jB, jC);
    }

    // ---- decoder: 2 balanced units per GEMM launch ----
    const float* d1prev = h1b[(Tc - 1) & 1];
    for (int s = 0; s < ML; s++) {
        float* d0cur = d0b[s & 1];
        float* d1cur = d1b[s & 1];
        {   // L1: d0_s = tanh(emb[tok]@Wih0 + P0 + b0);  P1 = d1_{s-1}@Whh1
            GemmJob jA = inv, jB = inv;
            jA.A = emb; jA.lda = Hc; jA.W = dWih0; jA.K = Hc;
            jA.gather = tok;
            jA.bias = db0; jA.addmat = P0; jA.ldadd = Hc;
            jA.C = d0cur; jA.ldc = Hc; jA.act = 1; jA.valid = 1;
            jB.A = d1prev; jB.lda = Hc; jB.W = dWhh1; jB.K = Hc;
            jB.C = P1; jB.ldc = Hc; jB.act = 0; jB.valid = 1;
            gemm3_kernel<128, 64, 64, 8, 4, 32>
                <<<dim3(Hc / 64, Bc / 64, 2), 128>>>(jA, jB, inv);
        }
        {   // L2: d1_s = tanh(d0_s@Wih1 + P1 + b1);  P0 = d0_s@Whh0 (for s+1)
            GemmJob jA = inv, jB = inv;
            jA.A = d0cur; jA.lda = Hc; jA.W = dWih1; jA.K = Hc;
            jA.bias = db1; jA.addmat = P1; jA.ldadd = Hc;
            jA.C = d1cur; jA.ldc = Hc; jA.act = 1; jA.valid = 1;
            jB.A = d0cur; jB.lda = Hc; jB.W = dWhh0; jB.K = Hc;
            jB.C = P0; jB.ldc = Hc; jB.act = 0; jB.valid = 1;
            gemm3_kernel<128, 64, 64, 8, 4, 32>
                <<<dim3(Hc / 64, Bc / 64, 2), 128>>>(jA, jB, inv);
        }
        logits_kernel<<<Bc / 32, 256>>>(d1cur, fcW, fcb, out, s, tok);
        d1prev = d1cur;
    }

    copy_hidden_kernel<<<(Bc * Hc + 255) / 256, 256>>>(
        d0b[(ML - 1) & 1], d1b[(ML - 1) & 1], out + (size_t)Bc * Vc * ML);
}

// round 7
// speedup vs baseline: 2.4055x; 2.4055x over previous
#include <cuda_runtime.h>
#include <cstdint>
#include <cstddef>

// Problem dims
#define Bc 256
#define Tc 128
#define Hc 1024
#define Vc 64
#define Lc 457
#define ML 64

typedef unsigned long long ull;

// ---------------- device scratch (no allocs allowed) ----------------
__device__ float g_U0[(size_t)Bc * Tc * Hc];   // x @ enc_Wih0^T + b0
__device__ float g_h0[2][Bc * Hc];
__device__ float g_h1[2][Bc * Hc];
__device__ float g_V [2][Bc * Hc];             // h0_t @ eWih1^T + b1
__device__ float g_d0[2][Bc * Hc];
__device__ float g_d1[2][Bc * Hc];
__device__ float g_P0[Bc * Hc];                // d0_{s-1} @ dWhh0^T (pre-rotated)
__device__ float g_P1[Bc * Hc];                // d1_{s-1} @ dWhh1^T
__device__ float g_zero[Bc * Hc];
__device__ int   g_tok[Bc];

// ---------------- packed fp32 helpers (sm_103a f32x2) ----------------
__device__ __forceinline__ ull dup2(float a) {
    ull r;
    asm("mov.b64 %0, {%1, %1};" : "=l"(r) : "r"(__float_as_uint(a)));
    return r;
}
__device__ __forceinline__ void ffma2(ull& d, ull a, ull b) {
    asm("fma.rn.f32x2 %0, %1, %2, %0;" : "+l"(d) : "l"(a), "l"(b));
}
__device__ __forceinline__ void unpk(ull v, float& lo, float& hi) {
    unsigned int a, b;
    asm("mov.b64 {%0, %1}, %2;" : "=r"(a), "=r"(b) : "l"(v));
    lo = __uint_as_float(a);
    hi = __uint_as_float(b);
}

// ---------------- GEMM job descriptor (single source) ----------------
struct GemmJob {
    const float* A; long lda; const float* W;  // C = act(A @ W^T + bias + addmat)
    int K;
    const int* gather;                          // optional row gather on A
    const float* bias; const float* addmat; long ldadd;
    float* C; long ldc; int act; int valid;
};

// ---------------- R2-proven tile loaders (BR rows x 16 k-cols) ----------------
template<int NT, int BR>
__device__ __forceinline__ void load_tile(
    const float* __restrict__ A, long lda, const int* __restrict__ gather,
    int r_base, int K, int k0, int tid, float (&r)[BR * 4 / NT][4])
{
    constexpr int NC = BR * 4 / NT;
#pragma unroll
    for (int i = 0; i < NC; i++) {
        int cid = tid + i * NT;
        int row = cid >> 2, kq = cid & 3;
        int kk = k0 + kq * 4;
        long arow = gather ? (long)__ldg(&gather[r_base + row]) : (long)(r_base + row);
        const float* p = A + arow * lda + kk;
        if (kk + 3 < K && ((((uintptr_t)p) & 15u) == 0)) {
            float4 v = *(const float4*)p;
            r[i][0] = v.x; r[i][1] = v.y; r[i][2] = v.z; r[i][3] = v.w;
        } else {
#pragma unroll
            for (int j = 0; j < 4; j++)
                r[i][j] = (kk + j < K) ? __ldg(p + j) : 0.0f;
        }
    }
}

template<int NT, int BR>
__device__ __forceinline__ void store_tile(
    float (&S)[16][BR], int tid, const float (&r)[BR * 4 / NT][4])
{
    constexpr int NC = BR * 4 / NT;
#pragma unroll
    for (int i = 0; i < NC; i++) {
        int cid = tid + i * NT;
        int row = cid >> 2, kq = cid & 3;
#pragma unroll
        for (int j = 0; j < 4; j++)
            S[kq * 4 + j][row] = r[i][j];
    }
}

// ---------------- R2-proven micro-kernel: TM x TN per thread via f32x2 ----------------
template<int BM, int BN, int TM, int TN>
__device__ __forceinline__ void mac_block(
    const float (&As)[16][BM], const float (&Ws)[16][BN],
    int r0, int c0, ull (&acc)[TM][TN / 2])
{
#pragma unroll
    for (int k = 0; k < 16; k++) {
        ull ad[TM];
#pragma unroll
        for (int i = 0; i < TM; i += 4) {
            float4 av = *(const float4*)&As[k][r0 + i];
            ad[i + 0] = dup2(av.x);
            ad[i + 1] = dup2(av.y);
            ad[i + 2] = dup2(av.z);
            ad[i + 3] = dup2(av.w);
        }
        ull wv[TN / 2];
#pragma unroll
        for (int p = 0; p < TN / 2; p += 2) {
            ulonglong2 w2 = *(const ulonglong2*)&Ws[k][c0 + 2 * p];
            wv[p] = w2.x;
            wv[p + 1] = w2.y;
        }
#pragma unroll
        for (int i = 0; i < TM; i++)
#pragma unroll
            for (int p = 0; p < TN / 2; p++)
                ffma2(acc[i][p], ad[i], wv[p]);
    }
}

// ---------------- K-staged double-buffered mainloop ----------------
template<int NT, int BM, int BN, int TM, int TN>
__device__ __forceinline__ void gemm_mainloop(
    const float* __restrict__ A, long lda,
    const float* __restrict__ W, int K,
    const int* __restrict__ gather,
    int m0, int n0, int tid, int r0, int c0,
    float (&As)[2][16][BM], float (&Ws)[2][16][BN],
    ull (&acc)[TM][TN / 2])
{
    constexpr int NCA = BM * 4 / NT;
    constexpr int NCW = BN * 4 / NT;
    float ar[NCA][4], wr[NCW][4];
    int nkb = (K + 15) / 16;

    load_tile<NT, BM>(A, lda, gather, m0, K, 0, tid, ar);
    load_tile<NT, BN>(W, (long)K, nullptr, n0, K, 0, tid, wr);
    store_tile<NT, BM>(As[0], tid, ar);
    store_tile<NT, BN>(Ws[0], tid, wr);
    __syncthreads();

    int buf = 0;
    for (int kb = 0; kb < nkb; kb++) {
        bool hn = (kb + 1 < nkb);
        if (hn) {
            load_tile<NT, BM>(A, lda, gather, m0, K, (kb + 1) * 16, tid, ar);
            load_tile<NT, BN>(W, (long)K, nullptr, n0, K, (kb + 1) * 16, tid, wr);
        }
        mac_block<BM, BN, TM, TN>(As[buf], Ws[buf], r0, c0, acc);
        if (hn) {
            store_tile<NT, BM>(As[buf ^ 1], tid, ar);
            store_tile<NT, BN>(Ws[buf ^ 1], tid, wr);
        }
        __syncthreads();
        buf ^= 1;
    }
}

// ---------------- generic GEMM kernel: up to 3 balanced jobs via blockIdx.z ----------------
template<int NT, int BM, int BN, int TM, int TN>
__global__ void __launch_bounds__(NT)
gemm3_kernel(GemmJob j0, GemmJob j1, GemmJob j2)
{
    GemmJob j = (blockIdx.z == 0) ? j0 : ((blockIdx.z == 1) ? j1 : j2);
    if (!j.valid) return;

    __shared__ float As[2][16][BM];
    __shared__ float Ws[2][16][BN];

    constexpr int CT = BN / TN;
    int tid = threadIdx.x;
    int m0 = blockIdx.y * BM;
    int n0 = blockIdx.x * BN;
    int ty = tid / CT, tx = tid % CT;
    int r0 = ty * TM, c0 = tx * TN;

    ull acc[TM][TN / 2] = {};
    gemm_mainloop<NT, BM, BN, TM, TN>(j.A, j.lda, j.W, j.K, j.gather,
                                      m0, n0, tid, r0, c0, As, Ws, acc);

#pragma unroll
    for (int i = 0; i < TM; i++) {
        int m = m0 + r0 + i;
        float o[TN];
#pragma unroll
        for (int p = 0; p < TN / 2; p++)
            unpk(acc[i][p], o[2 * p], o[2 * p + 1]);
#pragma unroll
        for (int q = 0; q < TN; q++) {
            float v = o[q];
            int n = n0 + c0 + q;
            if (j.bias)   v += __ldg(&j.bias[n]);
            if (j.addmat) v += __ldg(&j.addmat[(long)m * j.ldadd + n]);
            if (j.act)    v = tanhf(v);
            o[q] = v;
        }
#pragma unroll
        for (int q = 0; q < TN; q += 4)
            *(float4*)&j.C[(long)m * j.ldc + n0 + c0 + q] = *(const float4*)&o[q];
    }
}

// ---------------- logits + argmax (R2-proven, one block per batch row) ----------------
__global__ void __launch_bounds__(256)
logits_kernel(const float* __restrict__ d1, const float* __restrict__ fcW,
              const float* __restrict__ fcb, float* __restrict__ out,
              int step, int* __restrict__ tok)
{
    __shared__ float hs[Hc];
    __shared__ float vals[Vc];
    int b = blockIdx.x, tid = threadIdx.x;

    *(float4*)&hs[tid * 4] = *(const float4*)&d1[(size_t)b * Hc + tid * 4];
    __syncthreads();

    int warp = tid >> 5, lane = tid & 31;
#pragma unroll
    for (int j = 0; j < 8; j++) {
        int v = warp * 8 + j;
        const float4* wp = (const float4*)&fcW[(size_t)v * Hc];
        float s = 0.0f;
#pragma unroll
        for (int i = 0; i < 8; i++) {
            float4 w4 = __ldg(&wp[lane + i * 32]);
            float4 h4 = *(const float4*)&hs[(lane + i * 32) * 4];
            s += w4.x * h4.x + w4.y * h4.y + w4.z * h4.z + w4.w * h4.w;
        }
#pragma unroll
        for (int o = 16; o; o >>= 1) s += __shfl_xor_sync(0xffffffffu, s, o);
        if (lane == 0) {
            s += fcb[v];
            vals[v] = s;
            out[((size_t)b * Vc + (size_t)v) * ML + (size_t)step] = s;
        }
    }
    __syncthreads();
    if (tid == 0) {
        float best = vals[0]; int bi = 0;
#pragma unroll
        for (int i = 1; i < Vc; i++)
            if (vals[i] > best) { best = vals[i]; bi = i; }   // first-max = jnp.argmax
        tok[b] = bi;
    }
}

__global__ void init_kernel(float* __restrict__ z, int* __restrict__ tok)
{
    int i = blockIdx.x * blockDim.x + threadIdx.x;
    if (i < Bc * Hc) z[i] = 0.0f;
    if (i < Bc) tok[i] = 0;
}

__global__ void copy_hidden_kernel(const float* __restrict__ d0,
                                   const float* __restrict__ d1,
                                   float* __restrict__ o)
{
    int i = blockIdx.x * blockDim.x + threadIdx.x;
    if (i < Bc * Hc) {
        o[i] = d0[i];
        o[Bc * Hc + i] = d1[i];
    }
}

// ---------------- host ----------------
extern "C" void kernel_launch(void* const* d_in, const int* in_sizes, int n_in,
                              void* d_out, int out_size)
{
    (void)in_sizes; (void)n_in; (void)out_size;
    const float* x     = (const float*)d_in[0];
    const float* emb   = (const float*)d_in[1];
    const float* eWih0 = (const float*)d_in[2];
    const float* eWhh0 = (const float*)d_in[3];
    const float* eb0   = (const float*)d_in[4];
    const float* eWih1 = (const float*)d_in[5];
    const float* eWhh1 = (const float*)d_in[6];
    const float* eb1   = (const float*)d_in[7];
    const float* dWih0 = (const float*)d_in[8];
    const float* dWhh0 = (const float*)d_in[9];
    const float* db0   = (const float*)d_in[10];
    const float* dWih1 = (const float*)d_in[11];
    const float* dWhh1 = (const float*)d_in[12];
    const float* db1   = (const float*)d_in[13];
    const float* fcW   = (const float*)d_in[14];
    const float* fcb   = (const float*)d_in[15];
    float* out = (float*)d_out;

    float *U0, *h0base, *h1base, *Vbase, *d0base, *d1base, *P0, *P1, *zero;
    int* tok;
    cudaGetSymbolAddress((void**)&U0, g_U0);
    cudaGetSymbolAddress((void**)&h0base, g_h0);
    cudaGetSymbolAddress((void**)&h1base, g_h1);
    cudaGetSymbolAddress((void**)&Vbase, g_V);
    cudaGetSymbolAddress((void**)&d0base, g_d0);
    cudaGetSymbolAddress((void**)&d1base, g_d1);
    cudaGetSymbolAddress((void**)&P0, g_P0);
    cudaGetSymbolAddress((void**)&P1, g_P1);
    cudaGetSymbolAddress((void**)&zero, g_zero);
    cudaGetSymbolAddress((void**)&tok, g_tok);

    float* h0b[2] = { h0base, h0base + (size_t)Bc * Hc };
    float* h1b[2] = { h1base, h1base + (size_t)Bc * Hc };
    float* Vb[2]  = { Vbase,  Vbase  + (size_t)Bc * Hc };
    float* d0b[2] = { d0base, d0base + (size_t)Bc * Hc };
    float* d1b[2] = { d1base, d1base + (size_t)Bc * Hc };

    init_kernel<<<(Bc * Hc + 255) / 256, 256>>>(zero, tok);

    GemmJob inv = {}; inv.valid = 0;

    // ---- precompute U0 = x_flat @ eWih0^T + b0 (R2 high-intensity config) ----
    {
        GemmJob j = {};
        j.A = x; j.lda = Lc; j.W = eWih0; j.K = Lc;
        j.bias = eb0;
        j.C = U0; j.ldc = Hc; j.act = 0; j.valid = 1;
        gemm3_kernel<256, 128, 128, 8, 8>
            <<<dim3(Hc / 128, (Bc * Tc) / 128, 1), 256>>>(j, inv, inv);
    }

    // ---- encoder: 3 balanced K=1024 units per launch (skewed chain, R3-verified) ----
    // launch t: A) h0_t = tanh(h0_{t-1}@Whh0 + U0[:,t])
    //           B) V_{t-1} = h0_{t-1}@Wih1 + b1
    //           C) h1_{t-2} = tanh(h1_{t-3}@Whh1 + V_{t-2})
    // t == Tc: slot A computes decoder bootstrap P0 = h0_final @ dWhh0
    for (int t = 0; t <= Tc + 1; t++) {
        GemmJob jA = inv, jB = inv, jC = inv;
        if (t < Tc) {
            jA.A = (t == 0) ? zero : h0b[(t - 1) & 1];
            jA.lda = Hc; jA.W = eWhh0; jA.K = Hc;
            jA.addmat = U0 + (size_t)t * Hc; jA.ldadd = (long)Tc * Hc;
            jA.C = h0b[t & 1]; jA.ldc = Hc; jA.act = 1; jA.valid = 1;
        } else if (t == Tc) {
            jA.A = h0b[(Tc - 1) & 1]; jA.lda = Hc; jA.W = dWhh0; jA.K = Hc;
            jA.C = P0; jA.ldc = Hc; jA.act = 0; jA.valid = 1;
        }
        if (t >= 1 && t <= Tc) {
            int s = t - 1;
            jB.A = h0b[s & 1]; jB.lda = Hc; jB.W = eWih1; jB.K = Hc;
            jB.bias = eb1;
            jB.C = Vb[s & 1]; jB.ldc = Hc; jB.act = 0; jB.valid = 1;
        }
        if (t >= 2) {
            int s = t - 2;
            jC.A = (s == 0) ? zero : h1b[(s - 1) & 1];
            jC.lda = Hc; jC.W = eWhh1; jC.K = Hc;
            jC.addmat = Vb[s & 1]; jC.ldadd = Hc;
            jC.C = h1b[s & 1]; jC.ldc = Hc; jC.act = 1; jC.valid = 1;
        }
        gemm3_kernel<256, 64, 64, 4, 4>
            <<<dim3(Hc / 64, Bc / 64, 3), 256>>>(jA, jB, jC);
    }

    // ---- decoder: 2 balanced K=1024 units per GEMM launch (P0/P1 pre-rotation) ----
    const float* d1prev = h1b[(Tc - 1) & 1];
    for (int s = 0; s < ML; s++) {
        float* d0cur = d0b[s & 1];
        float* d1cur = d1b[s & 1];
        {   // L1: d0_s = tanh(emb[tok]@Wih0 + P0 + b0);  P1 = d1_{s-1}@Whh1
            GemmJob jA = inv, jB = inv;
            jA.A = emb; jA.lda = Hc; jA.W = dWih0; jA.K = Hc;
            jA.gather = tok;
            jA.bias = db0; jA.addmat = P0; jA.ldadd = Hc;
            jA.C = d0cur; jA.ldc = Hc; jA.act = 1; jA.valid = 1;
            jB.A = d1prev; jB.lda = Hc; jB.W = dWhh1; jB.K = Hc;
            jB.C = P1; jB.ldc = Hc; jB.act = 0; jB.valid = 1;
            gemm3_kernel<256, 64, 64, 4, 4>
                <<<dim3(Hc / 64, Bc / 64, 2), 256>>>(jA, jB, inv);
        }
        {   // L2: d1_s = tanh(d0_s@Wih1 + P1 + b1);  P0 = d0_s@Whh0 (for s+1)
            GemmJob jA = inv, jB = inv;
            jA.A = d0cur; jA.lda = Hc; jA.W = dWih1; jA.K = Hc;
            jA.bias = db1; jA.addmat = P1; jA.ldadd = Hc;
            jA.C = d1cur; jA.ldc = Hc; jA.act = 1; jA.valid = 1;
            jB.A = d0cur; jB.lda = Hc; jB.W = dWhh0; jB.K = Hc;
            jB.C = P0; jB.ldc = Hc; jB.act = 0; jB.valid = 1;
            gemm3_kernel<256, 64, 64, 4, 4>
                <<<dim3(Hc / 64, Bc / 64, 2), 256>>>(jA, jB, inv);
        }
        logits_kernel<<<Bc, 256>>>(d1cur, fcW, fcb, out, s, tok);
        d1prev = d1cur;
    }

    copy_hidden_kernel<<<(Bc * Hc + 255) / 256, 256>>>(
        d0b[(ML - 1) & 1], d1b[(ML - 1) & 1], out + (size_t)Bc * Vc * ML);
}